// round 3
// baseline (speedup 1.0000x reference)
#include <cuda_runtime.h>

// StealNMSLoss — fused single-pass implementation, branchless bin selection,
// interior-block fast path (no clamp/reflect arithmetic off the border).
// Inputs: d_in[0] = true_labels (4,19,512,512) f32, d_in[1] = pred_labels f32.
// Output: scalar f32 = -(1/B) * sum over (C,H,W) of term.
//
// Math notes:
//  * Sobel (normalized /8) applied twice with replicate ('edge') padding at EACH
//    stage -> second stage samples gx/gy at CLAMPED coordinates (nested pad).
//  * theta = arctan(gyy*sign(eps-gxy)/(gxx+eps)); angle bins on [0,180) are
//    equivalent (arctan monotone) to comparing z against tan(22.5)=t1,
//    tan(67.5)=t2. Division avoided: compare sign-corrected numerator nn
//    against t*|den|.
//      horizontal  : z in [-t1,  t1)   -> taps +-(0,1)
//      counter-diag: z in [ t1,  t2)   -> taps +-(1,-1)   (fliplr(eye) kernel)
//      vertical    : z >= t2 or z < -t2-> taps +-(1,0)
//      leading-diag: z in (-t2, -t1)   -> taps +-(1,1)    (eye kernel)
//      z == -t2 exactly, or 0/0 (NaN)  -> no bin
//  * e = exp(0.1*pred); f = 3-tap sum of e with reflect padding.
//  * term = mask * log(clip(e/(f+eps), eps, 1)); bins mutually exclusive ->
//    at most one filter per pixel.

#define HH 512
#define WW 512
#define NIMG 76          // B*C = 4*19
#define EPSC 1e-7f

__device__ double g_nms_acc;

__global__ void nms_init_kernel() { g_nms_acc = 0.0; }

__global__ void nms_fin_kernel(float* out) {
    out[0] = (float)(-g_nms_acc * 0.25);  // mean over B=4, negate
}

__launch_bounds__(256)
__global__ void nms_main_kernel(const float* __restrict__ tl,
                                const float* __restrict__ pl) {
    __shared__ float st[36][37];   // t tile, halo 2, clamped
    __shared__ float se[34][35];   // exp(0.1*p) tile, halo 1, reflected
    __shared__ float sgx[34][35];  // Sobel gx at clamped coords, halo 1
    __shared__ float sgy[34][35];  // Sobel gy at clamped coords, halo 1

    const int x0 = blockIdx.x * 32;
    const int y0 = blockIdx.y * 32;
    const size_t base = (size_t)blockIdx.z * (HH * WW);
    const float* t = tl + base;
    const float* p = pl + base;
    const int tid = threadIdx.y * 32 + threadIdx.x;

    const bool border = (blockIdx.x == 0) | (blockIdx.x == (WW / 32 - 1)) |
                        (blockIdx.y == 0) | (blockIdx.y == (HH / 32 - 1));

    if (!border) {
        // -------- interior fast path: no clamp/reflect arithmetic --------
        const float* tb = t + (size_t)(y0 - 2) * WW + (x0 - 2);
        for (int i = tid; i < 36 * 36; i += 256) {
            int iy = i / 36, ix = i - iy * 36;
            st[iy][ix] = __ldg(tb + (size_t)iy * WW + ix);
        }
        const float* pb = p + (size_t)(y0 - 1) * WW + (x0 - 1);
        for (int i = tid; i < 34 * 34; i += 256) {
            int iy = i / 34, ix = i - iy * 34;
            se[iy][ix] = __expf(0.1f * __ldg(pb + (size_t)iy * WW + ix));
        }
        __syncthreads();
        for (int i = tid; i < 34 * 34; i += 256) {
            int iy = i / 34, ix = i - iy * 34;
            int ay = iy + 1, ax = ix + 1;
            float A = st[ay - 1][ax - 1], B = st[ay - 1][ax], C = st[ay - 1][ax + 1];
            float D = st[ay][ax - 1],                          E = st[ay][ax + 1];
            float F = st[ay + 1][ax - 1], G = st[ay + 1][ax], Hv = st[ay + 1][ax + 1];
            sgx[iy][ix] = 0.125f * ((C - A) + 2.0f * (E - D) + (Hv - F));
            sgy[iy][ix] = 0.125f * ((F - A) + 2.0f * (G - B) + (Hv - C));
        }
        __syncthreads();
    } else {
        // -------- border path: full clamp (t) / reflect (e) / nested clamp --------
        for (int i = tid; i < 36 * 36; i += 256) {
            int iy = i / 36, ix = i - iy * 36;
            int gy = y0 - 2 + iy; gy = gy < 0 ? 0 : (gy > HH - 1 ? HH - 1 : gy);
            int gx = x0 - 2 + ix; gx = gx < 0 ? 0 : (gx > WW - 1 ? WW - 1 : gx);
            st[iy][ix] = __ldg(t + (size_t)gy * WW + gx);
        }
        for (int i = tid; i < 34 * 34; i += 256) {
            int iy = i / 34, ix = i - iy * 34;
            int gy = y0 - 1 + iy; gy = gy < 0 ? -gy : (gy >= HH ? 2 * HH - 2 - gy : gy);
            int gx = x0 - 1 + ix; gx = gx < 0 ? -gx : (gx >= WW ? 2 * WW - 2 - gx : gx);
            se[iy][ix] = __expf(0.1f * __ldg(p + (size_t)gy * WW + gx));
        }
        __syncthreads();
        for (int i = tid; i < 34 * 34; i += 256) {
            int iy = i / 34, ix = i - iy * 34;
            int cy = y0 - 1 + iy; cy = cy < 0 ? 0 : (cy > HH - 1 ? HH - 1 : cy);
            int cx = x0 - 1 + ix; cx = cx < 0 ? 0 : (cx > WW - 1 ? WW - 1 : cx);
            int ay = cy - y0 + 2;   // index into st for t(clamp(cy))
            int ax = cx - x0 + 2;
            float A = st[ay - 1][ax - 1], B = st[ay - 1][ax], C = st[ay - 1][ax + 1];
            float D = st[ay][ax - 1],                          E = st[ay][ax + 1];
            float F = st[ay + 1][ax - 1], G = st[ay + 1][ax], Hv = st[ay + 1][ax + 1];
            sgx[iy][ix] = 0.125f * ((C - A) + 2.0f * (E - D) + (Hv - F));
            sgy[iy][ix] = 0.125f * ((F - A) + 2.0f * (G - B) + (Hv - C));
        }
        __syncthreads();
    }

    // ---- stage 2: per-pixel second derivatives, branchless bin, loss term ----
    float acc = 0.0f;
    const int tx = threadIdx.x;
#pragma unroll
    for (int rr = 0; rr < 4; rr++) {
        int ty = threadIdx.y + rr * 8;
        float tc = st[ty + 2][tx + 2];
        if (tc > 0.0f) {
            float gxx = 0.125f * ((sgx[ty][tx + 2] - sgx[ty][tx])
                       + 2.0f * (sgx[ty + 1][tx + 2] - sgx[ty + 1][tx])
                       + (sgx[ty + 2][tx + 2] - sgx[ty + 2][tx]));
            float gxy = 0.125f * ((sgy[ty][tx + 2] - sgy[ty][tx])
                       + 2.0f * (sgy[ty + 1][tx + 2] - sgy[ty + 1][tx])
                       + (sgy[ty + 2][tx + 2] - sgy[ty + 2][tx]));
            float gyy = 0.125f * ((sgy[ty + 2][tx] - sgy[ty][tx])
                       + 2.0f * (sgy[ty + 2][tx + 1] - sgy[ty][tx + 1])
                       + (sgy[ty + 2][tx + 2] - sgy[ty][tx + 2]));

            float sv = EPSC - gxy;
            float s = (sv > 0.0f) ? 1.0f : ((sv < 0.0f) ? -1.0f : 0.0f);
            float nmr = gyy * s;
            float den = gxx + EPSC;
            float nn = (den < 0.0f) ? -nmr : nmr;   // sign-corrected numerator
            float dd = fabsf(den);
            float th1 = 0.41421356237309503f * dd;  // tan(22.5 deg)*|den|
            float th2 = 2.41421356237309510f * dd;  // tan(67.5 deg)*|den|

            // Mutually exclusive bins (branchless predicates)
            bool vert = (nn >= th2) | (nn < -th2);          // [67.5,112.5)
            bool cd   = !vert & (nn >= th1);                // [22.5,67.5)
            bool hz   = !vert & !cd & (nn >= -th1);         // [0,22.5)U[157.5,180)
            bool ld   = !vert & !cd & !hz & (nn > -th2);    // (112.5,157.5)
            bool valid = (vert | cd | hz | ld) & !((nn == 0.0f) & (dd == 0.0f));

            if (valid) {
                // tap direction (dy,dx): h=(0,1) v=(1,0) cd=(1,-1) ld=(1,1)
                int dy = hz ? 0 : 1;
                int dx = vert ? 0 : (cd ? -1 : 1);
                int cyy = ty + 1, cxx = tx + 1;
                float ec = se[cyy][cxx];
                float f = se[cyy - dy][cxx - dx] + ec + se[cyy + dy][cxx + dx];
                float r = __fdividef(ec, f + EPSC);
                r = fminf(fmaxf(r, EPSC), 1.0f);
                acc += __logf(r);
            }
        }
    }

    // ---- block reduction -> double atomic ----
#pragma unroll
    for (int off = 16; off > 0; off >>= 1)
        acc += __shfl_down_sync(0xffffffffu, acc, off);
    __shared__ float wsum[8];
    if ((tid & 31) == 0) wsum[tid >> 5] = acc;
    __syncthreads();
    if (tid < 8) {
        float v = wsum[tid];
        v += __shfl_down_sync(0xffu, v, 4);
        v += __shfl_down_sync(0xffu, v, 2);
        v += __shfl_down_sync(0xffu, v, 1);
        if (tid == 0) atomicAdd(&g_nms_acc, (double)v);
    }
}

extern "C" void kernel_launch(void* const* d_in, const int* in_sizes, int n_in,
                              void* d_out, int out_size) {
    const float* tl = (const float*)d_in[0];
    const float* pl = (const float*)d_in[1];
    float* out = (float*)d_out;

    nms_init_kernel<<<1, 1>>>();
    dim3 grid(WW / 32, HH / 32, NIMG);
    dim3 block(32, 8);
    nms_main_kernel<<<grid, block>>>(tl, pl);
    nms_fin_kernel<<<1, 1>>>(out);
}